// round 1
// baseline (speedup 1.0000x reference)
#include <cuda_runtime.h>
#include <math.h>
#include <stdint.h>
#include <stddef.h>

#define Bb 32
#define Tt 512
#define Dd 256
#define Hh 1024
#define G4 4096
#define BT (Bb*Tt)          // 16384
#define NCTA 128
#define UPC 8               // hidden units per CTA

// ---------------- scratch (device globals; no allocation allowed) ----------------
__device__ float g_xg[(size_t)BT * G4];   // 256 MB: gate preactivations / reused as act+lin
__device__ float g_hseq[(size_t)BT * Hh]; // 64 MB: per-layer output sequence
__device__ float g_hbuf[2 * Hh * Bb];     // recurrent h double buffer, layout [parity][unit][batch]
__device__ unsigned int g_cnt;            // grid barrier counter

#define SCAN_SMEM ((32*1024 + 128*33 + 1024) * 4)   // W slice + h chunk + xg stage = 152064 B

// ---------------- helpers ----------------
__device__ __forceinline__ float sigm(float x) { return 1.f / (1.f + expf(-x)); }
__device__ __forceinline__ float gelu_exact(float x) {
    return 0.5f * x * (1.f + erff(x * 0.70710678118654752440f));
}

// ---------------- reset (barrier counter + h double buffer) ----------------
__global__ void reset_scan_state() {
    int i = blockIdx.x * blockDim.x + threadIdx.x;
    if (i == 0) g_cnt = 0u;
    for (int j = i; j < 2 * Hh * Bb; j += gridDim.x * blockDim.x) g_hbuf[j] = 0.f;
}

// ---------------- fp32 GEMM: C[m][n] = sum_k A[m][k]*Bw[n][k] + b1[n] (+ b2[n]) ----------------
// M,N multiples of 128; K multiple of 8.
__global__ void __launch_bounds__(256) gemm_nt_bias(
    const float* __restrict__ A, const float* __restrict__ Bw,
    const float* __restrict__ b1, const float* __restrict__ b2,
    float* __restrict__ C, int M, int N, int K)
{
    __shared__ float As[8][132];
    __shared__ float Bs[8][132];
    const int tid = threadIdx.x;
    const int bm = blockIdx.y << 7;
    const int bn = blockIdx.x << 7;
    const int tx = tid & 15;       // 16 cols of threads
    const int ty = tid >> 4;       // 16 rows of threads
    const int lrow = tid >> 1;     // 0..127 (tile row loaded by this thread)
    const int lc4  = (tid & 1) << 2;

    const float* Ap = A + (size_t)(bm + lrow) * K + lc4;
    const float* Bp = Bw + (size_t)(bn + lrow) * K + lc4;

    float acc[8][8];
#pragma unroll
    for (int i = 0; i < 8; i++)
#pragma unroll
        for (int j = 0; j < 8; j++) acc[i][j] = 0.f;

    for (int k0 = 0; k0 < K; k0 += 8) {
        float4 av = *(const float4*)(Ap + k0);
        float4 bv = *(const float4*)(Bp + k0);
        As[lc4+0][lrow] = av.x; As[lc4+1][lrow] = av.y;
        As[lc4+2][lrow] = av.z; As[lc4+3][lrow] = av.w;
        Bs[lc4+0][lrow] = bv.x; Bs[lc4+1][lrow] = bv.y;
        Bs[lc4+2][lrow] = bv.z; Bs[lc4+3][lrow] = bv.w;
        __syncthreads();
#pragma unroll
        for (int k = 0; k < 8; k++) {
            float4 a0 = *(const float4*)&As[k][ty*8];
            float4 a1 = *(const float4*)&As[k][ty*8+4];
            float4 c0 = *(const float4*)&Bs[k][tx*8];
            float4 c1 = *(const float4*)&Bs[k][tx*8+4];
            float a[8] = {a0.x,a0.y,a0.z,a0.w,a1.x,a1.y,a1.z,a1.w};
            float b[8] = {c0.x,c0.y,c0.z,c0.w,c1.x,c1.y,c1.z,c1.w};
#pragma unroll
            for (int i = 0; i < 8; i++)
#pragma unroll
                for (int j = 0; j < 8; j++) acc[i][j] += a[i] * b[j];
        }
        __syncthreads();
    }

    float bs[8];
#pragma unroll
    for (int j = 0; j < 8; j++) {
        int n = bn + tx*8 + j;
        bs[j] = b1[n] + (b2 ? b2[n] : 0.f);
    }
#pragma unroll
    for (int i = 0; i < 8; i++) {
        float* cp = C + (size_t)(bm + ty*8 + i) * N + bn + tx*8;
#pragma unroll
        for (int j = 0; j < 8; j++) cp[j] = acc[i][j] + bs[j];
    }
}

// ---------------- persistent LSTM scan ----------------
// 128 CTAs x 256 threads; CTA c owns units [c*8, c*8+8).
// thread: uu = tid>>5 (warp == unit), b = tid&31 (lane == batch).
__global__ void __launch_bounds__(256, 1) lstm_scan(
    const float* __restrict__ W_hh,   // [4H][H]
    const float* __restrict__ xg,     // [B][T][4H] precomputed gates (+biases)
    float* __restrict__ hseq)         // [B][T][H] output sequence
{
    extern __shared__ float smem[];
    float* sW  = smem;                // 32*1024  (rows: uu*4+gate)
    float* sH  = smem + 32*1024;      // 128*33   (h chunk, [k][b], pad 33)
    float* sXG = sH + 128*33;         // 1024     ([b][gate][u])

    const int tid = threadIdx.x;
    const int u0  = blockIdx.x * UPC;

    // Load this CTA's W_hh slice into SMEM: row r = uu*4+g  <-  W_hh[g*H + u0+uu][*]
    for (int i = tid; i < 32*256; i += 256) {   // 8192 float4
        int r  = i >> 8;
        int c4 = (i & 255) << 2;
        int uu = r >> 2, g = r & 3;
        float4 v = *(const float4*)(W_hh + (size_t)(g*Hh + u0 + uu) * Hh + c4);
        *(float4*)(sW + r*1024 + c4) = v;
    }

    const int uu = tid >> 5;
    const int b  = tid & 31;
    const float* sW0 = sW + (uu*4+0)*1024;
    const float* sW1 = sW + (uu*4+1)*1024;
    const float* sW2 = sW + (uu*4+2)*1024;
    const float* sW3 = sW + (uu*4+3)*1024;

    // xg staging mapping: thread -> (batch pb, gate pg, 4-unit half ph)
    const int pb = tid >> 3;
    const int pg = (tid >> 1) & 3;
    const int ph = (tid & 1) << 2;
    const float* xg_base = xg + (size_t)pb * Tt * G4 + pg*1024 + u0 + ph;
    float4 px = *(const float4*)xg_base;   // prefetch t = 0

    float c_state = 0.f;
    unsigned bar = 0;

    for (int t = 0; t < Tt; t++) {
        // stage prefetched xg for this step; kick off next step's load
        {
            float* d = sXG + pb*32 + pg*8 + ph;
            d[0] = px.x; d[1] = px.y; d[2] = px.z; d[3] = px.w;
            int tn = (t + 1 < Tt) ? (t + 1) : t;
            px = *(const float4*)(xg_base + (size_t)tn * G4);
        }

        float a0 = 0.f, a1 = 0.f, a2 = 0.f, a3 = 0.f;
        const int rp = t & 1;
        const float* hprev = g_hbuf + rp * (Hh * Bb);

        for (int k0 = 0; k0 < Hh; k0 += 128) {
            // stage 128x32 h chunk (coalesced gmem, conflict-free smem)
#pragma unroll
            for (int i = 0; i < 4; i++) {
                int e  = tid + i*256;          // float4 index 0..1023
                int kk = e >> 3;
                int b4 = (e & 7) << 2;
                float4 hv = __ldcg((const float4*)(hprev + (k0 + kk)*Bb + b4));
                float* d = sH + kk*33 + b4;
                d[0] = hv.x; d[1] = hv.y; d[2] = hv.z; d[3] = hv.w;
            }
            __syncthreads();
#pragma unroll
            for (int kk = 0; kk < 32; kk++) {
                const int k = kk << 2;
                float4 wi = *(const float4*)(sW0 + k0 + k);
                float4 wf = *(const float4*)(sW1 + k0 + k);
                float4 wg = *(const float4*)(sW2 + k0 + k);
                float4 wo = *(const float4*)(sW3 + k0 + k);
                float h0v = sH[(k+0)*33 + b];
                float h1v = sH[(k+1)*33 + b];
                float h2v = sH[(k+2)*33 + b];
                float h3v = sH[(k+3)*33 + b];
                a0 += wi.x*h0v; a0 += wi.y*h1v; a0 += wi.z*h2v; a0 += wi.w*h3v;
                a1 += wf.x*h0v; a1 += wf.y*h1v; a1 += wf.z*h2v; a1 += wf.w*h3v;
                a2 += wg.x*h0v; a2 += wg.y*h1v; a2 += wg.z*h2v; a2 += wg.w*h3v;
                a3 += wo.x*h0v; a3 += wo.y*h1v; a3 += wo.z*h2v; a3 += wo.w*h3v;
            }
            __syncthreads();
        }

        // add precomputed input gates
        a0 += sXG[b*32 + 0*8 + uu];
        a1 += sXG[b*32 + 1*8 + uu];
        a2 += sXG[b*32 + 2*8 + uu];
        a3 += sXG[b*32 + 3*8 + uu];

        float ig = sigm(a0);
        float fg = sigm(a1);
        float gg = tanhf(a2);
        float og = sigm(a3);
        c_state = fg * c_state + ig * gg;
        float hval = og * tanhf(c_state);

        // write new h (coalesced; .cg to stay L2-coherent across CTAs)
        __stcg(g_hbuf + (1 - rp) * (Hh * Bb) + (u0 + uu)*Bb + b, hval);
        hseq[((size_t)b * Tt + t) * Hh + u0 + uu] = hval;

        // grid barrier (all 128 CTAs resident by construction)
        __syncthreads();
        if (tid == 0) {
            __threadfence();
            atomicAdd(&g_cnt, 1u);
            bar += NCTA;
            while (*((volatile unsigned int*)&g_cnt) < bar) { }
            __threadfence();
        }
        __syncthreads();
    }
}

// ---------------- LayerNorm -> GELU (one block per row) ----------------
__global__ void ln_gelu_kernel(const float* __restrict__ X, const float* __restrict__ w,
                               const float* __restrict__ bv, float* __restrict__ Y)
{
    __shared__ float red[2][8];
    const int row = blockIdx.x;
    const int tid = threadIdx.x;
    float4 v = ((const float4*)(X + (size_t)row * Hh))[tid];
    float s = v.x + v.y + v.z + v.w;
    float q = v.x*v.x + v.y*v.y + v.z*v.z + v.w*v.w;
    int lane = tid & 31, wid = tid >> 5;
#pragma unroll
    for (int o = 16; o; o >>= 1) {
        s += __shfl_xor_sync(0xffffffffu, s, o);
        q += __shfl_xor_sync(0xffffffffu, q, o);
    }
    if (lane == 0) { red[0][wid] = s; red[1][wid] = q; }
    __syncthreads();
    if (wid == 0) {
        s = (lane < 8) ? red[0][lane] : 0.f;
        q = (lane < 8) ? red[1][lane] : 0.f;
#pragma unroll
        for (int o = 4; o; o >>= 1) {
            s += __shfl_xor_sync(0xffffffffu, s, o);
            q += __shfl_xor_sync(0xffffffffu, q, o);
        }
        if (lane == 0) { red[0][0] = s; red[1][0] = q; }
    }
    __syncthreads();
    float mu  = red[0][0] * (1.f / Hh);
    float var = red[1][0] * (1.f / Hh) - mu * mu;
    float rstd = rsqrtf(var + 1e-5f);
    float4 wv = ((const float4*)w)[tid];
    float4 bb = ((const float4*)bv)[tid];
    float4 y;
    y.x = gelu_exact((v.x - mu) * rstd * wv.x + bb.x);
    y.y = gelu_exact((v.y - mu) * rstd * wv.y + bb.y);
    y.z = gelu_exact((v.z - mu) * rstd * wv.z + bb.z);
    y.w = gelu_exact((v.w - mu) * rstd * wv.w + bb.w);
    ((float4*)(Y + (size_t)row * Hh))[tid] = y;
}

// ---------------- GELU -> LayerNorm (one block per row) ----------------
__global__ void gelu_ln_kernel(const float* __restrict__ X, const float* __restrict__ w,
                               const float* __restrict__ bv, float* __restrict__ Y)
{
    __shared__ float red[2][8];
    const int row = blockIdx.x;
    const int tid = threadIdx.x;
    float4 v = ((const float4*)(X + (size_t)row * Hh))[tid];
    v.x = gelu_exact(v.x); v.y = gelu_exact(v.y);
    v.z = gelu_exact(v.z); v.w = gelu_exact(v.w);
    float s = v.x + v.y + v.z + v.w;
    float q = v.x*v.x + v.y*v.y + v.z*v.z + v.w*v.w;
    int lane = tid & 31, wid = tid >> 5;
#pragma unroll
    for (int o = 16; o; o >>= 1) {
        s += __shfl_xor_sync(0xffffffffu, s, o);
        q += __shfl_xor_sync(0xffffffffu, q, o);
    }
    if (lane == 0) { red[0][wid] = s; red[1][wid] = q; }
    __syncthreads();
    if (wid == 0) {
        s = (lane < 8) ? red[0][lane] : 0.f;
        q = (lane < 8) ? red[1][lane] : 0.f;
#pragma unroll
        for (int o = 4; o; o >>= 1) {
            s += __shfl_xor_sync(0xffffffffu, s, o);
            q += __shfl_xor_sync(0xffffffffu, q, o);
        }
        if (lane == 0) { red[0][0] = s; red[1][0] = q; }
    }
    __syncthreads();
    float mu  = red[0][0] * (1.f / Hh);
    float var = red[1][0] * (1.f / Hh) - mu * mu;
    float rstd = rsqrtf(var + 1e-5f);
    float4 wv = ((const float4*)w)[tid];
    float4 bb = ((const float4*)bv)[tid];
    float4 y;
    y.x = (v.x - mu) * rstd * wv.x + bb.x;
    y.y = (v.y - mu) * rstd * wv.y + bb.y;
    y.z = (v.z - mu) * rstd * wv.z + bb.z;
    y.w = (v.w - mu) * rstd * wv.w + bb.w;
    ((float4*)(Y + (size_t)row * Hh))[tid] = y;
}

// ---------------- driver ----------------
extern "C" void kernel_launch(void* const* d_in, const int* in_sizes, int n_in,
                              void* d_out, int out_size)
{
    const float* bone  = (const float*)d_in[0];
    const float* W_ih0 = (const float*)d_in[1];
    const float* W_hh0 = (const float*)d_in[2];
    const float* b_ih0 = (const float*)d_in[3];
    const float* b_hh0 = (const float*)d_in[4];
    const float* W_ih1 = (const float*)d_in[5];
    const float* W_hh1 = (const float*)d_in[6];
    const float* b_ih1 = (const float*)d_in[7];
    const float* b_hh1 = (const float*)d_in[8];
    const float* ln1w  = (const float*)d_in[9];
    const float* ln1b  = (const float*)d_in[10];
    const float* linw  = (const float*)d_in[11];
    const float* linb  = (const float*)d_in[12];
    const float* ln2w  = (const float*)d_in[13];
    const float* ln2b  = (const float*)d_in[14];
    float* out = (float*)d_out;

    float *xg = nullptr, *hseq = nullptr;
    cudaGetSymbolAddress((void**)&xg, g_xg);
    cudaGetSymbolAddress((void**)&hseq, g_hseq);
    float* act = xg;                               // reuse after gates consumed
    float* lin = xg + (size_t)BT * Hh;             // disjoint region

    cudaFuncSetAttribute(lstm_scan, cudaFuncAttributeMaxDynamicSharedMemorySize, SCAN_SMEM);

    dim3 gemm_g4(G4/128, BT/128);
    dim3 gemm_h(Hh/128, BT/128);

    // layer 0
    gemm_nt_bias<<<gemm_g4, 256>>>(bone, W_ih0, b_ih0, b_hh0, xg, BT, G4, Dd);
    reset_scan_state<<<64, 256>>>();
    lstm_scan<<<NCTA, 256, SCAN_SMEM>>>(W_hh0, xg, hseq);

    // layer 1
    gemm_nt_bias<<<gemm_g4, 256>>>(hseq, W_ih1, b_ih1, b_hh1, xg, BT, G4, Hh);
    reset_scan_state<<<64, 256>>>();
    lstm_scan<<<NCTA, 256, SCAN_SMEM>>>(W_hh1, xg, hseq);

    // post: LN -> GELU -> Linear -> GELU -> LN
    ln_gelu_kernel<<<BT, 256>>>(hseq, ln1w, ln1b, act);
    gemm_nt_bias<<<gemm_h, 256>>>(act, linw, linb, nullptr, lin, BT, Hh, Hh);
    gelu_ln_kernel<<<BT, 256>>>(lin, ln2w, ln2b, out);
}